// round 7
// baseline (speedup 1.0000x reference)
#include <cuda_runtime.h>
#include <cuda_bf16.h>
#include <math.h>

#define VV   50000
#define VB   64
#define VS   512
#define VE   256
#define VH   512
#define VT   64
#define G3H  1536

typedef unsigned long long ull;

// ---------------------------------------------------------------------------
// Scratch (device globals; runtime allocation is forbidden)
// ---------------------------------------------------------------------------
__device__ float g_gi[(size_t)VS * VB * G3H];            // [s][b][3H]
// states slot 0 = h0(zeros); slot s+1 = h after step s.
// Layout per slot: [c=k/4][b][k%4]  (chunk-interleaved)
__device__ float g_states[(size_t)(VS + 1) * VB * VH];
__device__ int g_tok[VB * VS];                            // int32 tokens [b][s]
__device__ unsigned g_bar_count;
__device__ unsigned g_bar_gen;

// ---------------------------------------------------------------------------
// f32x2 helpers
// ---------------------------------------------------------------------------
__device__ __forceinline__ ull fma2(ull a, ull b, ull c) {
    ull d;
    asm("fma.rn.f32x2 %0, %1, %2, %3;" : "=l"(d) : "l"(a), "l"(b), "l"(c));
    return d;
}
__device__ __forceinline__ ull pack2(float x, float y) {
    ull d;
    asm("mov.b64 %0, {%1, %2};" : "=l"(d) : "f"(x), "f"(y));
    return d;
}
__device__ __forceinline__ void unpk(ull a, float& x, float& y) {
    asm("mov.b64 {%0, %1}, %2;" : "=f"(x), "=f"(y) : "l"(a));
}
__device__ __forceinline__ float sum2(ull a) {
    float x, y; unpk(a, x, y); return x + y;
}

// ---------------------------------------------------------------------------
// Token prologue: detect int32 vs int64 on device, convert+clamp into g_tok.
// ---------------------------------------------------------------------------
__global__ void tok_kernel(const int* __restrict__ raw) {
    __shared__ int is64;
    const int tid = threadIdx.x;
    if (tid == 0) {
        int z = 1;
        for (int i = 0; i < 32; i++)
            if (raw[2 * i + 1] != 0) { z = 0; break; }
        is64 = z;
    }
    __syncthreads();
    const int stride = is64 ? 2 : 1;
    for (int i = tid; i < VB * VS; i += 256) {
        int t = raw[(size_t)i * stride];
        t = (t < 0) ? 0 : ((t >= VV) ? (VV - 1) : t);
        g_tok[i] = t;
    }
}

// ---------------------------------------------------------------------------
// Init: zero d_out, zero h0 slot, reset barrier (runs every replay)
// ---------------------------------------------------------------------------
__global__ void init_kernel(float* out, int out_size) {
    int i = blockIdx.x * blockDim.x + threadIdx.x;
    int stride = gridDim.x * blockDim.x;
    for (int j = i; j < out_size; j += stride) out[j] = 0.0f;
    for (int j = i; j < VB * VH; j += stride) g_states[j] = 0.0f;
    if (i == 0) { g_bar_count = 0u; g_bar_gen = 0u; }
}

// ---------------------------------------------------------------------------
// Kernel A: gi[s][b][:] = emb[tokens[b][s]] @ W_ih^T + b_ih   (proven)
// ---------------------------------------------------------------------------
__global__ void __launch_bounds__(256) gi_kernel(const float* __restrict__ emb,
                                                 const float* __restrict__ Wih,
                                                 const float* __restrict__ bih) {
    __shared__ __align__(16) float As[32 * 64];    // [k][m]
    __shared__ __align__(16) float Bs[32 * 128];   // [k][g]
    __shared__ int tok[64];

    const int tid = threadIdx.x;
    const int s = blockIdx.y;
    const int g0 = blockIdx.x * 128;

    if (tid < 64) tok[tid] = g_tok[tid * VS + s];

    const int rg = tid & 15;
    const int cg = tid >> 4;

    ull acc[4][4];
    {
        const float4 b0 = *(const float4*)&bih[g0 + cg * 8];
        const float4 b1 = *(const float4*)&bih[g0 + cg * 8 + 4];
        ull p0 = pack2(b0.x, b0.y), p1 = pack2(b0.z, b0.w);
        ull p2 = pack2(b1.x, b1.y), p3 = pack2(b1.z, b1.w);
#pragma unroll
        for (int i = 0; i < 4; i++) {
            acc[i][0] = p0; acc[i][1] = p1; acc[i][2] = p2; acc[i][3] = p3;
        }
    }
    __syncthreads();

    for (int kt = 0; kt < VE; kt += 32) {
        {
            const int arow = tid >> 2, kq = tid & 3;
            const float* src = emb + (size_t)tok[arow] * VE + kt + kq * 8;
            const float4 v0 = *(const float4*)(src);
            const float4 v1 = *(const float4*)(src + 4);
            const int kb = kq * 8;
            As[(kb + 0) * 64 + arow] = v0.x; As[(kb + 1) * 64 + arow] = v0.y;
            As[(kb + 2) * 64 + arow] = v0.z; As[(kb + 3) * 64 + arow] = v0.w;
            As[(kb + 4) * 64 + arow] = v1.x; As[(kb + 5) * 64 + arow] = v1.y;
            As[(kb + 6) * 64 + arow] = v1.z; As[(kb + 7) * 64 + arow] = v1.w;
        }
        {
            const int grow = tid >> 1, kh = tid & 1;
            const float* src = Wih + (size_t)(g0 + grow) * VE + kt + kh * 16;
#pragma unroll
            for (int q = 0; q < 4; q++) {
                const float4 v = *(const float4*)(src + q * 4);
                const int kb = kh * 16 + q * 4;
                Bs[(kb + 0) * 128 + grow] = v.x; Bs[(kb + 1) * 128 + grow] = v.y;
                Bs[(kb + 2) * 128 + grow] = v.z; Bs[(kb + 3) * 128 + grow] = v.w;
            }
        }
        __syncthreads();
#pragma unroll
        for (int k = 0; k < 32; k++) {
            const float4 av = *(const float4*)&As[k * 64 + rg * 4];
            const ull pa0 = pack2(av.x, av.x), pa1 = pack2(av.y, av.y);
            const ull pa2 = pack2(av.z, av.z), pa3 = pack2(av.w, av.w);
            const ulonglong2 bA = *(const ulonglong2*)&Bs[k * 128 + cg * 8];
            const ulonglong2 bB = *(const ulonglong2*)&Bs[k * 128 + cg * 8 + 4];
            acc[0][0] = fma2(pa0, bA.x, acc[0][0]); acc[0][1] = fma2(pa0, bA.y, acc[0][1]);
            acc[0][2] = fma2(pa0, bB.x, acc[0][2]); acc[0][3] = fma2(pa0, bB.y, acc[0][3]);
            acc[1][0] = fma2(pa1, bA.x, acc[1][0]); acc[1][1] = fma2(pa1, bA.y, acc[1][1]);
            acc[1][2] = fma2(pa1, bB.x, acc[1][2]); acc[1][3] = fma2(pa1, bB.y, acc[1][3]);
            acc[2][0] = fma2(pa2, bA.x, acc[2][0]); acc[2][1] = fma2(pa2, bA.y, acc[2][1]);
            acc[2][2] = fma2(pa2, bB.x, acc[2][2]); acc[2][3] = fma2(pa2, bB.y, acc[2][3]);
            acc[3][0] = fma2(pa3, bA.x, acc[3][0]); acc[3][1] = fma2(pa3, bA.y, acc[3][1]);
            acc[3][2] = fma2(pa3, bB.x, acc[3][2]); acc[3][3] = fma2(pa3, bB.y, acc[3][3]);
        }
        __syncthreads();
    }

#pragma unroll
    for (int i = 0; i < 4; i++) {
        float o0, o1, o2, o3, o4, o5, o6, o7;
        unpk(acc[i][0], o0, o1); unpk(acc[i][1], o2, o3);
        unpk(acc[i][2], o4, o5); unpk(acc[i][3], o6, o7);
        float* dst = g_gi + (size_t)(s * VB + rg * 4 + i) * G3H + g0 + cg * 8;
        float4 w0; w0.x = o0; w0.y = o1; w0.z = o2; w0.w = o3;
        float4 w1; w1.x = o4; w1.y = o5; w1.z = o6; w1.w = o7;
        *(float4*)(dst) = w0;
        *(float4*)(dst + 4) = w1;
    }
}

// ---------------------------------------------------------------------------
// Kernel B: persistent GRU, 512 threads, k split 8 ways.
// thread = (ul:4, bq:16, ks:8): partial dots over its k-eighth (16 chunks)
// for 4 batch rows. Each 64-thread ks-group copies+reads its own 16KB eighth
// (2 pipelined 8KB cp.async groups, named barrier 1+ks). Reduction via SMEM
// part[g*8+ks][b*4+ul]; epilogue on tid<256; fast sigmoid/tanh via __expf.
// ---------------------------------------------------------------------------
#define GRU_CTAS 128
#define WPITCH   516
#define EFLOATS  4096                        // eighth = 16 chunks x 256 floats
#define PART_OFF (12 * WPITCH + VB * VH)     // after weights + h (32768)
#define GRU_SMEM ((PART_OFF + 24 * 256) * 4) // (6192+32768+6144)*4 = 180416 B

__global__ void __launch_bounds__(512, 1) gru_kernel(const float* __restrict__ Whh,
                                                     const float* __restrict__ bhh) {
    extern __shared__ __align__(16) float dyn[];
    float* ws   = dyn;                        // 12 * WPITCH
    float* part = dyn + PART_OFF;             // 24 * 256

    const int tid = threadIdx.x;
    const int cta = blockIdx.x;
    const int ul = tid & 3;                   // unit (0..3)
    const int bq = (tid >> 2) & 15;           // base batch row (0..15)
    const int ks = tid >> 6;                  // k-eighth (0..7)
    const int u  = cta * 4 + ul;

    float* hq = dyn + 12 * WPITCH + ks * EFLOATS;
    const int lane64 = tid & 63;

    for (int idx = tid; idx < 12 * VH; idx += 512) {
        const int lr = idx >> 9, k = idx & 511;
        const int g = lr >> 2, uu = lr & 3;
        ws[lr * WPITCH + k] = Whh[(size_t)(g * VH + cta * 4 + uu) * VH + k];
    }
    const float bR = bhh[u], bZ = bhh[VH + u], bN = bhh[2 * VH + u];
    __syncthreads();

    // chunk pointers, pre-offset to this thread's eighth (16 chunks)
    const ulonglong2* wR = (const ulonglong2*)&ws[(0 + ul) * WPITCH] + ks * 16;
    const ulonglong2* wZ = (const ulonglong2*)&ws[(4 + ul) * WPITCH] + ks * 16;
    const ulonglong2* wN = (const ulonglong2*)&ws[(8 + ul) * WPITCH] + ks * 16;

    const unsigned hq_s = (unsigned)__cvta_generic_to_shared(hq);

#define CITER(c)                                                            \
    {                                                                       \
        const ulonglong2 r2 = wR[(c)];                                      \
        const ulonglong2 z2 = wZ[(c)];                                      \
        const ulonglong2 n2 = wN[(c)];                                      \
        const float* hb = hq + (c) * 256;                                   \
        const ulonglong2 h0 = *(const ulonglong2*)(hb + bq * 4);            \
        const ulonglong2 h1 = *(const ulonglong2*)(hb + (bq + 16) * 4);     \
        const ulonglong2 hx2 = *(const ulonglong2*)(hb + (bq + 32) * 4);    \
        const ulonglong2 hx3 = *(const ulonglong2*)(hb + (bq + 48) * 4);    \
        aR0 = fma2(h0.x, r2.x, aR0);  aR0 = fma2(h0.y, r2.y, aR0);          \
        aR1 = fma2(h1.x, r2.x, aR1);  aR1 = fma2(h1.y, r2.y, aR1);          \
        aR2 = fma2(hx2.x, r2.x, aR2); aR2 = fma2(hx2.y, r2.y, aR2);         \
        aR3 = fma2(hx3.x, r2.x, aR3); aR3 = fma2(hx3.y, r2.y, aR3);         \
        aZ0 = fma2(h0.x, z2.x, aZ0);  aZ0 = fma2(h0.y, z2.y, aZ0);          \
        aZ1 = fma2(h1.x, z2.x, aZ1);  aZ1 = fma2(h1.y, z2.y, aZ1);          \
        aZ2 = fma2(hx2.x, z2.x, aZ2); aZ2 = fma2(hx2.y, z2.y, aZ2);         \
        aZ3 = fma2(hx3.x, z2.x, aZ3); aZ3 = fma2(hx3.y, z2.y, aZ3);         \
        aN0 = fma2(h0.x, n2.x, aN0);  aN0 = fma2(h0.y, n2.y, aN0);          \
        aN1 = fma2(h1.x, n2.x, aN1);  aN1 = fma2(h1.y, n2.y, aN1);          \
        aN2 = fma2(hx2.x, n2.x, aN2); aN2 = fma2(hx2.y, n2.y, aN2);         \
        aN3 = fma2(hx3.x, n2.x, aN3); aN3 = fma2(hx3.y, n2.y, aN3);         \
    }

    for (int s = 0; s < VS; s++) {
        const float* hf = g_states + (size_t)s * (VB * VH);
        const char* gsrc = (const char*)(hf + ks * EFLOATS);

        // copy own eighth in two pipelined 8KB halves (8 x 16B per thread each)
#pragma unroll
        for (int j = 0; j < 8; j++) {
            const int off = (j * 64 + lane64) * 16;
            asm volatile("cp.async.cg.shared.global [%0], [%1], 16;"
                         :: "r"(hq_s + off), "l"(gsrc + off) : "memory");
        }
        asm volatile("cp.async.commit_group;" ::: "memory");
#pragma unroll
        for (int j = 8; j < 16; j++) {
            const int off = (j * 64 + lane64) * 16;
            asm volatile("cp.async.cg.shared.global [%0], [%1], 16;"
                         :: "r"(hq_s + off), "l"(gsrc + off) : "memory");
        }
        asm volatile("cp.async.commit_group;" ::: "memory");

        // early independent loads (epilogue only; tid<256)
        float gr = 0.0f, gz = 0.0f, gn = 0.0f, hp = 0.0f;
        if (tid < 256) {
            const float* gis = g_gi + (size_t)(s * VB + (tid >> 2)) * G3H;
            gr = __ldg(gis + u);
            gz = __ldg(gis + VH + u);
            gn = __ldg(gis + 2 * VH + u);
            hp = __ldcg(hf + cta * 256 + tid);
        }

        ull aR0 = 0, aR1 = 0, aR2 = 0, aR3 = 0;
        ull aZ0 = 0, aZ1 = 0, aZ2 = 0, aZ3 = 0;
        ull aN0 = 0, aN1 = 0, aN2 = 0, aN3 = 0;

        asm volatile("cp.async.wait_group 1;" ::: "memory");
        asm volatile("bar.sync %0, 64;" :: "r"(1 + ks) : "memory");
#pragma unroll
        for (int c = 0; c < 8; c++) CITER(c);
        asm volatile("cp.async.wait_group 0;" ::: "memory");
        asm volatile("bar.sync %0, 64;" :: "r"(1 + ks) : "memory");
#pragma unroll
        for (int c = 8; c < 16; c++) CITER(c);

        // store partials: part[(g*8+ks)*256 + b*4 + ul]
        {
            float* pR = part + (0 * 8 + ks) * 256 + bq * 4 + ul;
            float* pZ = part + (1 * 8 + ks) * 256 + bq * 4 + ul;
            float* pN = part + (2 * 8 + ks) * 256 + bq * 4 + ul;
            pR[0] = sum2(aR0); pR[64] = sum2(aR1); pR[128] = sum2(aR2); pR[192] = sum2(aR3);
            pZ[0] = sum2(aZ0); pZ[64] = sum2(aZ1); pZ[128] = sum2(aZ2); pZ[192] = sum2(aZ3);
            pN[0] = sum2(aN0); pN[64] = sum2(aN1); pN[128] = sum2(aN2); pN[192] = sum2(aN3);
        }
        __syncthreads();

        // cross-ks reduction + epilogue (tid<256 -> (eb, ul))
        if (tid < 256) {
            float dr = 0.0f, dz = 0.0f, dn = 0.0f;
#pragma unroll
            for (int k8 = 0; k8 < 8; k8++) {
                dr += part[(0 * 8 + k8) * 256 + tid];
                dz += part[(1 * 8 + k8) * 256 + tid];
                dn += part[(2 * 8 + k8) * 256 + tid];
            }
            const float r = __fdividef(1.0f, 1.0f + __expf(-(gr + dr + bR)));
            const float z = __fdividef(1.0f, 1.0f + __expf(-(gz + dz + bZ)));
            const float xn = gn + r * (dn + bN);
            const float n = 1.0f - __fdividef(2.0f, __expf(2.0f * xn) + 1.0f);
            const float hnew = (1.0f - z) * n + z * hp;
            __stcg(g_states + (size_t)(s + 1) * (VB * VH) + cta * 256 + tid, hnew);
        }

        // grid-wide step barrier (proven)
        __syncthreads();
        if (tid == 0) {
            __threadfence();
            const unsigned arrived = atomicAdd(&g_bar_count, 1u);
            if (arrived == GRU_CTAS - 1) {
                atomicExch(&g_bar_count, 0u);
                __threadfence();
                atomicExch(&g_bar_gen, (unsigned)(s + 1));
            } else {
                while (*(volatile unsigned*)&g_bar_gen < (unsigned)(s + 1)) {}
            }
            __threadfence();
        }
        __syncthreads();
    }
#undef CITER
}

// ---------------------------------------------------------------------------
// Kernel C: tag_logits = states @ W_tag^T + b_tag ; preds (proven)
// ---------------------------------------------------------------------------
#define WT_PITCH 68

__global__ void __launch_bounds__(256) tag_kernel(const float* __restrict__ Wtag,
                                                  const float* __restrict__ btag,
                                                  float* __restrict__ out,
                                                  int preds_off, int write_preds) {
    __shared__ __align__(16) float Wt[128 * WT_PITCH];

    const int tid = threadIdx.x;
    const int r = tid >> 2;
    const int tg4 = tid & 3;
    const int m = blockIdx.x * 64 + r;        // m = b*512 + s
    const int bb = m >> 9, s = m & 511;
    const float* st = g_states + (size_t)(s + 1) * (VB * VH) + bb * 4;

    float acc[16];
#pragma unroll
    for (int j = 0; j < 16; j++) acc[j] = btag[tg4 * 16 + j];

    for (int cc = 0; cc < 4; cc++) {
        __syncthreads();
        for (int idx = tid; idx < VT * 128; idx += 256) {
            const int tg = idx >> 7, kk = idx & 127;
            Wt[kk * WT_PITCH + tg] = Wtag[(size_t)tg * VH + cc * 128 + kk];
        }
        __syncthreads();
#pragma unroll 4
        for (int c = 0; c < 32; c++) {
            const float4 a4 = __ldg((const float4*)(st + (size_t)(cc * 32 + c) * 256));
#pragma unroll
            for (int kq = 0; kq < 4; kq++) {
                const float av = (kq == 0) ? a4.x : (kq == 1) ? a4.y : (kq == 2) ? a4.z : a4.w;
                const float4* w4p = (const float4*)&Wt[(c * 4 + kq) * WT_PITCH + tg4 * 16];
                const float4 w0 = w4p[0], w1 = w4p[1], w2 = w4p[2], w3 = w4p[3];
                acc[0]  = fmaf(av, w0.x, acc[0]);  acc[1]  = fmaf(av, w0.y, acc[1]);
                acc[2]  = fmaf(av, w0.z, acc[2]);  acc[3]  = fmaf(av, w0.w, acc[3]);
                acc[4]  = fmaf(av, w1.x, acc[4]);  acc[5]  = fmaf(av, w1.y, acc[5]);
                acc[6]  = fmaf(av, w1.z, acc[6]);  acc[7]  = fmaf(av, w1.w, acc[7]);
                acc[8]  = fmaf(av, w2.x, acc[8]);  acc[9]  = fmaf(av, w2.y, acc[9]);
                acc[10] = fmaf(av, w2.z, acc[10]); acc[11] = fmaf(av, w2.w, acc[11]);
                acc[12] = fmaf(av, w3.x, acc[12]); acc[13] = fmaf(av, w3.y, acc[13]);
                acc[14] = fmaf(av, w3.z, acc[14]); acc[15] = fmaf(av, w3.w, acc[15]);
            }
        }
    }

    {
        float* dst = out + (size_t)m * VT + tg4 * 16;
#pragma unroll
        for (int q = 0; q < 4; q++) {
            float4 v;
            v.x = acc[q * 4]; v.y = acc[q * 4 + 1];
            v.z = acc[q * 4 + 2]; v.w = acc[q * 4 + 3];
            *(float4*)(dst + q * 4) = v;
        }
    }

    if (write_preds) {
        float v = acc[0]; int bi = 0;
#pragma unroll
        for (int j = 1; j < 16; j++) { if (acc[j] > v) { v = acc[j]; bi = j; } }
        bi += tg4 * 16;
#pragma unroll
        for (int off = 2; off >= 1; off >>= 1) {
            const float v2 = __shfl_down_sync(0xFFFFFFFFu, v, off, 4);
            const int i2 = __shfl_down_sync(0xFFFFFFFFu, bi, off, 4);
            if (v2 > v) { v = v2; bi = i2; }
        }
        if (tg4 == 0) {
            const int t = g_tok[bb * VS + s];
            out[preds_off + m] = (t != 0) ? (float)bi : 0.0f;
        }
    }
}

// ---------------------------------------------------------------------------
extern "C" void kernel_launch(void* const* d_in, const int* in_sizes, int n_in,
                              void* d_out, int out_size) {
    const int*   tokens_raw = (const int*)d_in[0];
    const float* emb  = (const float*)d_in[1];
    const float* Wih  = (const float*)d_in[2];
    const float* Whh  = (const float*)d_in[3];
    const float* bih  = (const float*)d_in[4];
    const float* bhh  = (const float*)d_in[5];
    const float* Wtag = (const float*)d_in[6];
    const float* btag = (const float*)d_in[7];
    float* out = (float*)d_out;

    const int logits_n = VB * VS * VT;                 // 2097152
    const int write_preds = (out_size >= logits_n + VB * VS) ? 1 : 0;

    static int smem_set = 0;
    if (!smem_set) {
        cudaFuncSetAttribute(gru_kernel, cudaFuncAttributeMaxDynamicSharedMemorySize, GRU_SMEM);
        smem_set = 1;
    }

    tok_kernel<<<1, 256>>>(tokens_raw);
    init_kernel<<<256, 256>>>(out, out_size);
    gi_kernel<<<dim3(12, 512), 256>>>(emb, Wih, bih);
    gru_kernel<<<GRU_CTAS, 512, GRU_SMEM>>>(Whh, bhh);
    tag_kernel<<<512, 256>>>(Wtag, btag, out, logits_n, write_preds);
}

// round 8
// speedup vs baseline: 1.1073x; 1.1073x over previous
#include <cuda_runtime.h>
#include <cuda_bf16.h>
#include <math.h>

#define VV   50000
#define VB   64
#define VS   512
#define VE   256
#define VH   512
#define VT   64
#define G3H  1536

typedef unsigned long long ull;

// ---------------------------------------------------------------------------
// Scratch (device globals; runtime allocation is forbidden)
// ---------------------------------------------------------------------------
__device__ float g_gi[(size_t)VS * VB * G3H];            // [s][b][3H]
// states slot 0 = h0(zeros); slot s+1 = h after step s.
// Layout per slot: [c=k/4][b][k%4]  (chunk-interleaved)
__device__ float g_states[(size_t)(VS + 1) * VB * VH];
__device__ int g_tok[VB * VS];                            // int32 tokens [b][s]
__device__ unsigned g_bar_count;

// ---------------------------------------------------------------------------
// f32x2 helpers
// ---------------------------------------------------------------------------
__device__ __forceinline__ ull fma2(ull a, ull b, ull c) {
    ull d;
    asm("fma.rn.f32x2 %0, %1, %2, %3;" : "=l"(d) : "l"(a), "l"(b), "l"(c));
    return d;
}
__device__ __forceinline__ ull pack2(float x, float y) {
    ull d;
    asm("mov.b64 %0, {%1, %2};" : "=l"(d) : "f"(x), "f"(y));
    return d;
}
__device__ __forceinline__ void unpk(ull a, float& x, float& y) {
    asm("mov.b64 {%0, %1}, %2;" : "=f"(x), "=f"(y) : "l"(a));
}
__device__ __forceinline__ float sum2(ull a) {
    float x, y; unpk(a, x, y); return x + y;
}
__device__ __forceinline__ ulonglong2 ldcg128v(const void* p) {
    ulonglong2 r;
    asm volatile("ld.global.cg.v2.u64 {%0, %1}, [%2];"
                 : "=l"(r.x), "=l"(r.y) : "l"(p));
    return r;
}

// ---------------------------------------------------------------------------
// Token prologue: detect int32 vs int64 on device, convert+clamp into g_tok.
// ---------------------------------------------------------------------------
__global__ void tok_kernel(const int* __restrict__ raw) {
    __shared__ int is64;
    const int tid = threadIdx.x;
    if (tid == 0) {
        int z = 1;
        for (int i = 0; i < 32; i++)
            if (raw[2 * i + 1] != 0) { z = 0; break; }
        is64 = z;
    }
    __syncthreads();
    const int stride = is64 ? 2 : 1;
    for (int i = tid; i < VB * VS; i += 256) {
        int t = raw[(size_t)i * stride];
        t = (t < 0) ? 0 : ((t >= VV) ? (VV - 1) : t);
        g_tok[i] = t;
    }
}

// ---------------------------------------------------------------------------
// Init: zero d_out, zero h0 slot, reset barrier (runs every replay)
// ---------------------------------------------------------------------------
__global__ void init_kernel(float* out, int out_size) {
    int i = blockIdx.x * blockDim.x + threadIdx.x;
    int stride = gridDim.x * blockDim.x;
    for (int j = i; j < out_size; j += stride) out[j] = 0.0f;
    for (int j = i; j < VB * VH; j += stride) g_states[j] = 0.0f;
    if (i == 0) g_bar_count = 0u;
}

// ---------------------------------------------------------------------------
// Kernel A: gi[s][b][:] = emb[tokens[b][s]] @ W_ih^T + b_ih   (proven)
// ---------------------------------------------------------------------------
__global__ void __launch_bounds__(256) gi_kernel(const float* __restrict__ emb,
                                                 const float* __restrict__ Wih,
                                                 const float* __restrict__ bih) {
    __shared__ __align__(16) float As[32 * 64];    // [k][m]
    __shared__ __align__(16) float Bs[32 * 128];   // [k][g]
    __shared__ int tok[64];

    const int tid = threadIdx.x;
    const int s = blockIdx.y;
    const int g0 = blockIdx.x * 128;

    if (tid < 64) tok[tid] = g_tok[tid * VS + s];

    const int rg = tid & 15;
    const int cg = tid >> 4;

    ull acc[4][4];
    {
        const float4 b0 = *(const float4*)&bih[g0 + cg * 8];
        const float4 b1 = *(const float4*)&bih[g0 + cg * 8 + 4];
        ull p0 = pack2(b0.x, b0.y), p1 = pack2(b0.z, b0.w);
        ull p2 = pack2(b1.x, b1.y), p3 = pack2(b1.z, b1.w);
#pragma unroll
        for (int i = 0; i < 4; i++) {
            acc[i][0] = p0; acc[i][1] = p1; acc[i][2] = p2; acc[i][3] = p3;
        }
    }
    __syncthreads();

    for (int kt = 0; kt < VE; kt += 32) {
        {
            const int arow = tid >> 2, kq = tid & 3;
            const float* src = emb + (size_t)tok[arow] * VE + kt + kq * 8;
            const float4 v0 = *(const float4*)(src);
            const float4 v1 = *(const float4*)(src + 4);
            const int kb = kq * 8;
            As[(kb + 0) * 64 + arow] = v0.x; As[(kb + 1) * 64 + arow] = v0.y;
            As[(kb + 2) * 64 + arow] = v0.z; As[(kb + 3) * 64 + arow] = v0.w;
            As[(kb + 4) * 64 + arow] = v1.x; As[(kb + 5) * 64 + arow] = v1.y;
            As[(kb + 6) * 64 + arow] = v1.z; As[(kb + 7) * 64 + arow] = v1.w;
        }
        {
            const int grow = tid >> 1, kh = tid & 1;
            const float* src = Wih + (size_t)(g0 + grow) * VE + kt + kh * 16;
#pragma unroll
            for (int q = 0; q < 4; q++) {
                const float4 v = *(const float4*)(src + q * 4);
                const int kb = kh * 16 + q * 4;
                Bs[(kb + 0) * 128 + grow] = v.x; Bs[(kb + 1) * 128 + grow] = v.y;
                Bs[(kb + 2) * 128 + grow] = v.z; Bs[(kb + 3) * 128 + grow] = v.w;
            }
        }
        __syncthreads();
#pragma unroll
        for (int k = 0; k < 32; k++) {
            const float4 av = *(const float4*)&As[k * 64 + rg * 4];
            const ull pa0 = pack2(av.x, av.x), pa1 = pack2(av.y, av.y);
            const ull pa2 = pack2(av.z, av.z), pa3 = pack2(av.w, av.w);
            const ulonglong2 bA = *(const ulonglong2*)&Bs[k * 128 + cg * 8];
            const ulonglong2 bB = *(const ulonglong2*)&Bs[k * 128 + cg * 8 + 4];
            acc[0][0] = fma2(pa0, bA.x, acc[0][0]); acc[0][1] = fma2(pa0, bA.y, acc[0][1]);
            acc[0][2] = fma2(pa0, bB.x, acc[0][2]); acc[0][3] = fma2(pa0, bB.y, acc[0][3]);
            acc[1][0] = fma2(pa1, bA.x, acc[1][0]); acc[1][1] = fma2(pa1, bA.y, acc[1][1]);
            acc[1][2] = fma2(pa1, bB.x, acc[1][2]); acc[1][3] = fma2(pa1, bB.y, acc[1][3]);
            acc[2][0] = fma2(pa2, bA.x, acc[2][0]); acc[2][1] = fma2(pa2, bA.y, acc[2][1]);
            acc[2][2] = fma2(pa2, bB.x, acc[2][2]); acc[2][3] = fma2(pa2, bB.y, acc[2][3]);
            acc[3][0] = fma2(pa3, bA.x, acc[3][0]); acc[3][1] = fma2(pa3, bA.y, acc[3][1]);
            acc[3][2] = fma2(pa3, bB.x, acc[3][2]); acc[3][3] = fma2(pa3, bB.y, acc[3][3]);
        }
        __syncthreads();
    }

#pragma unroll
    for (int i = 0; i < 4; i++) {
        float o0, o1, o2, o3, o4, o5, o6, o7;
        unpk(acc[i][0], o0, o1); unpk(acc[i][1], o2, o3);
        unpk(acc[i][2], o4, o5); unpk(acc[i][3], o6, o7);
        float* dst = g_gi + (size_t)(s * VB + rg * 4 + i) * G3H + g0 + cg * 8;
        float4 w0; w0.x = o0; w0.y = o1; w0.z = o2; w0.w = o3;
        float4 w1; w1.x = o4; w1.y = o5; w1.z = o6; w1.w = o7;
        *(float4*)(dst) = w0;
        *(float4*)(dst + 4) = w1;
    }
}

// ---------------------------------------------------------------------------
// Kernel B: persistent GRU, 512 threads, k split 8 ways, DIRECT-LDG h path.
// thread = (ul:4, bq:16, ks:8). h chunks read straight from L2 with a 4-deep
// software-pipelined ring (each warp h-load = one 128B line). No cp.async, no
// wait_group, no named barriers -> zero sync points in the compute segment.
// Lean release/acquire grid barrier (monotonic counter).
// ---------------------------------------------------------------------------
#define GRU_CTAS 128
#define WPITCH   516

__global__ void __launch_bounds__(512, 1) gru_kernel(const float* __restrict__ Whh,
                                                     const float* __restrict__ bhh) {
    __shared__ __align__(16) float ws[12 * WPITCH];
    __shared__ __align__(16) float part[24 * 256];

    const int tid = threadIdx.x;
    const int cta = blockIdx.x;
    const int ul = tid & 3;                   // unit (0..3)
    const int bq = (tid >> 2) & 15;           // base batch row (0..15)
    const int ks = tid >> 6;                  // k-eighth (0..7)
    const int u  = cta * 4 + ul;

    for (int idx = tid; idx < 12 * VH; idx += 512) {
        const int lr = idx >> 9, k = idx & 511;
        const int g = lr >> 2, uu = lr & 3;
        ws[lr * WPITCH + k] = Whh[(size_t)(g * VH + cta * 4 + uu) * VH + k];
    }
    const float bR = bhh[u], bZ = bhh[VH + u], bN = bhh[2 * VH + u];
    __syncthreads();

    // weight chunk pointers, pre-offset to this thread's eighth (16 chunks)
    const ulonglong2* wR = (const ulonglong2*)&ws[(0 + ul) * WPITCH] + ks * 16;
    const ulonglong2* wZ = (const ulonglong2*)&ws[(4 + ul) * WPITCH] + ks * 16;
    const ulonglong2* wN = (const ulonglong2*)&ws[(8 + ul) * WPITCH] + ks * 16;

    // 4-slot ring of h chunk data (4 batch rows per chunk)
    ulonglong2 hA[4], hB[4], hC[4], hD[4];

#define PRE(c, sl)                                                          \
    {                                                                       \
        const char* p = hb8 + (c) * 1024 + bq * 16;                         \
        hA[sl] = ldcg128v(p);                                               \
        hB[sl] = ldcg128v(p + 256);                                         \
        hC[sl] = ldcg128v(p + 512);                                         \
        hD[sl] = ldcg128v(p + 768);                                         \
    }

#define COMP(c, sl)                                                         \
    {                                                                       \
        const ulonglong2 r2 = wR[(c)];                                      \
        const ulonglong2 z2 = wZ[(c)];                                      \
        const ulonglong2 n2 = wN[(c)];                                      \
        aR0 = fma2(hA[sl].x, r2.x, aR0); aR0 = fma2(hA[sl].y, r2.y, aR0);   \
        aR1 = fma2(hB[sl].x, r2.x, aR1); aR1 = fma2(hB[sl].y, r2.y, aR1);   \
        aR2 = fma2(hC[sl].x, r2.x, aR2); aR2 = fma2(hC[sl].y, r2.y, aR2);   \
        aR3 = fma2(hD[sl].x, r2.x, aR3); aR3 = fma2(hD[sl].y, r2.y, aR3);   \
        aZ0 = fma2(hA[sl].x, z2.x, aZ0); aZ0 = fma2(hA[sl].y, z2.y, aZ0);   \
        aZ1 = fma2(hB[sl].x, z2.x, aZ1); aZ1 = fma2(hB[sl].y, z2.y, aZ1);   \
        aZ2 = fma2(hC[sl].x, z2.x, aZ2); aZ2 = fma2(hC[sl].y, z2.y, aZ2);   \
        aZ3 = fma2(hD[sl].x, z2.x, aZ3); aZ3 = fma2(hD[sl].y, z2.y, aZ3);   \
        aN0 = fma2(hA[sl].x, n2.x, aN0); aN0 = fma2(hA[sl].y, n2.y, aN0);   \
        aN1 = fma2(hB[sl].x, n2.x, aN1); aN1 = fma2(hB[sl].y, n2.y, aN1);   \
        aN2 = fma2(hC[sl].x, n2.x, aN2); aN2 = fma2(hC[sl].y, n2.y, aN2);   \
        aN3 = fma2(hD[sl].x, n2.x, aN3); aN3 = fma2(hD[sl].y, n2.y, aN3);   \
    }

    for (int s = 0; s < VS; s++) {
        const float* hf = g_states + (size_t)s * (VB * VH);
        const char* hb8 = (const char*)hf + ks * 16 * 1024;   // this eighth

        // prime the ring (16 independent 16B LDGs in flight)
        PRE(0, 0); PRE(1, 1); PRE(2, 2); PRE(3, 3);

        // early independent loads (epilogue only; tid<256)
        float gr = 0.0f, gz = 0.0f, gn = 0.0f, hp = 0.0f;
        if (tid < 256) {
            const float* gis = g_gi + (size_t)(s * VB + (tid >> 2)) * G3H;
            gr = __ldg(gis + u);
            gz = __ldg(gis + VH + u);
            gn = __ldg(gis + 2 * VH + u);
            hp = __ldcg(hf + cta * 256 + tid);
        }

        ull aR0 = 0, aR1 = 0, aR2 = 0, aR3 = 0;
        ull aZ0 = 0, aZ1 = 0, aZ2 = 0, aZ3 = 0;
        ull aN0 = 0, aN1 = 0, aN2 = 0, aN3 = 0;

#pragma unroll
        for (int c = 0; c < 16; c++) {
            COMP(c, c & 3);
            if (c < 12) PRE(c + 4, c & 3);
        }

        // store partials: part[(g*8+ks)*256 + b*4 + ul]
        {
            float* pR = part + (0 * 8 + ks) * 256 + bq * 4 + ul;
            float* pZ = part + (1 * 8 + ks) * 256 + bq * 4 + ul;
            float* pN = part + (2 * 8 + ks) * 256 + bq * 4 + ul;
            pR[0] = sum2(aR0); pR[64] = sum2(aR1); pR[128] = sum2(aR2); pR[192] = sum2(aR3);
            pZ[0] = sum2(aZ0); pZ[64] = sum2(aZ1); pZ[128] = sum2(aZ2); pZ[192] = sum2(aZ3);
            pN[0] = sum2(aN0); pN[64] = sum2(aN1); pN[128] = sum2(aN2); pN[192] = sum2(aN3);
        }
        __syncthreads();

        // cross-ks reduction + epilogue (tid<256 -> (b, ul))
        if (tid < 256) {
            float dr = 0.0f, dz = 0.0f, dn = 0.0f;
#pragma unroll
            for (int k8 = 0; k8 < 8; k8++) {
                dr += part[(0 * 8 + k8) * 256 + tid];
                dz += part[(1 * 8 + k8) * 256 + tid];
                dn += part[(2 * 8 + k8) * 256 + tid];
            }
            const float r = __fdividef(1.0f, 1.0f + __expf(-(gr + dr + bR)));
            const float z = __fdividef(1.0f, 1.0f + __expf(-(gz + dz + bZ)));
            const float xn = gn + r * (dn + bN);
            const float n = 1.0f - __fdividef(2.0f, __expf(2.0f * xn) + 1.0f);
            const float hnew = (1.0f - z) * n + z * hp;
            __stcg(g_states + (size_t)(s + 1) * (VB * VH) + cta * 256 + tid, hnew);
        }

        // lean grid barrier: release-add on monotonic counter, acquire poll
        __syncthreads();
        if (tid == 0) {
            asm volatile("red.release.gpu.global.add.u32 [%0], %1;"
                         :: "l"(&g_bar_count), "r"(1u) : "memory");
            const unsigned target = (unsigned)(s + 1) * GRU_CTAS;
            unsigned v;
            do {
                asm volatile("ld.acquire.gpu.global.u32 %0, [%1];"
                             : "=r"(v) : "l"(&g_bar_count) : "memory");
            } while (v < target);
        }
        __syncthreads();
    }
#undef PRE
#undef COMP
}

// ---------------------------------------------------------------------------
// Kernel C: tag_logits = states @ W_tag^T + b_tag ; preds (proven)
// ---------------------------------------------------------------------------
#define WT_PITCH 68

__global__ void __launch_bounds__(256) tag_kernel(const float* __restrict__ Wtag,
                                                  const float* __restrict__ btag,
                                                  float* __restrict__ out,
                                                  int preds_off, int write_preds) {
    __shared__ __align__(16) float Wt[128 * WT_PITCH];

    const int tid = threadIdx.x;
    const int r = tid >> 2;
    const int tg4 = tid & 3;
    const int m = blockIdx.x * 64 + r;        // m = b*512 + s
    const int bb = m >> 9, s = m & 511;
    const float* st = g_states + (size_t)(s + 1) * (VB * VH) + bb * 4;

    float acc[16];
#pragma unroll
    for (int j = 0; j < 16; j++) acc[j] = btag[tg4 * 16 + j];

    for (int cc = 0; cc < 4; cc++) {
        __syncthreads();
        for (int idx = tid; idx < VT * 128; idx += 256) {
            const int tg = idx >> 7, kk = idx & 127;
            Wt[kk * WT_PITCH + tg] = Wtag[(size_t)tg * VH + cc * 128 + kk];
        }
        __syncthreads();
#pragma unroll 4
        for (int c = 0; c < 32; c++) {
            const float4 a4 = __ldg((const float4*)(st + (size_t)(cc * 32 + c) * 256));
#pragma unroll
            for (int kq = 0; kq < 4; kq++) {
                const float av = (kq == 0) ? a4.x : (kq == 1) ? a4.y : (kq == 2) ? a4.z : a4.w;
                const float4* w4p = (const float4*)&Wt[(c * 4 + kq) * WT_PITCH + tg4 * 16];
                const float4 w0 = w4p[0], w1 = w4p[1], w2 = w4p[2], w3 = w4p[3];
                acc[0]  = fmaf(av, w0.x, acc[0]);  acc[1]  = fmaf(av, w0.y, acc[1]);
                acc[2]  = fmaf(av, w0.z, acc[2]);  acc[3]  = fmaf(av, w0.w, acc[3]);
                acc[4]  = fmaf(av, w1.x, acc[4]);  acc[5]  = fmaf(av, w1.y, acc[5]);
                acc[6]  = fmaf(av, w1.z, acc[6]);  acc[7]  = fmaf(av, w1.w, acc[7]);
                acc[8]  = fmaf(av, w2.x, acc[8]);  acc[9]  = fmaf(av, w2.y, acc[9]);
                acc[10] = fmaf(av, w2.z, acc[10]); acc[11] = fmaf(av, w2.w, acc[11]);
                acc[12] = fmaf(av, w3.x, acc[12]); acc[13] = fmaf(av, w3.y, acc[13]);
                acc[14] = fmaf(av, w3.z, acc[14]); acc[15] = fmaf(av, w3.w, acc[15]);
            }
        }
    }

    {
        float* dst = out + (size_t)m * VT + tg4 * 16;
#pragma unroll
        for (int q = 0; q < 4; q++) {
            float4 v;
            v.x = acc[q * 4]; v.y = acc[q * 4 + 1];
            v.z = acc[q * 4 + 2]; v.w = acc[q * 4 + 3];
            *(float4*)(dst + q * 4) = v;
        }
    }

    if (write_preds) {
        float v = acc[0]; int bi = 0;
#pragma unroll
        for (int j = 1; j < 16; j++) { if (acc[j] > v) { v = acc[j]; bi = j; } }
        bi += tg4 * 16;
#pragma unroll
        for (int off = 2; off >= 1; off >>= 1) {
            const float v2 = __shfl_down_sync(0xFFFFFFFFu, v, off, 4);
            const int i2 = __shfl_down_sync(0xFFFFFFFFu, bi, off, 4);
            if (v2 > v) { v = v2; bi = i2; }
        }
        if (tg4 == 0) {
            const int t = g_tok[bb * VS + s];
            out[preds_off + m] = (t != 0) ? (float)bi : 0.0f;
        }
    }
}

// ---------------------------------------------------------------------------
extern "C" void kernel_launch(void* const* d_in, const int* in_sizes, int n_in,
                              void* d_out, int out_size) {
    const int*   tokens_raw = (const int*)d_in[0];
    const float* emb  = (const float*)d_in[1];
    const float* Wih  = (const float*)d_in[2];
    const float* Whh  = (const float*)d_in[3];
    const float* bih  = (const float*)d_in[4];
    const float* bhh  = (const float*)d_in[5];
    const float* Wtag = (const float*)d_in[6];
    const float* btag = (const float*)d_in[7];
    float* out = (float*)d_out;

    const int logits_n = VB * VS * VT;                 // 2097152
    const int write_preds = (out_size >= logits_n + VB * VS) ? 1 : 0;

    tok_kernel<<<1, 256>>>(tokens_raw);
    init_kernel<<<256, 256>>>(out, out_size);
    gi_kernel<<<dim3(12, 512), 256>>>(emb, Wih, bih);
    gru_kernel<<<GRU_CTAS, 512>>>(Whh, bhh);
    tag_kernel<<<512, 256>>>(Wtag, btag, out, logits_n, write_preds);
}